// round 6
// baseline (speedup 1.0000x reference)
#include <cuda_runtime.h>
#include <cuda_bf16.h>
#include <mma.h>
#include <cstdint>

using namespace nvcuda;

__device__ __forceinline__ float2 cmul(float2 a, float2 b) {
    return make_float2(fmaf(a.x, b.x, -a.y * b.y), fmaf(a.x, b.y, a.y * b.x));
}

// Cody-Waite reduction to ~[-pi, pi]; exact for |ph| <~ 25000
__device__ __forceinline__ float red2pi(float ph) {
    float q = rintf(ph * 0.15915494309f);
    ph = fmaf(q, -6.28125f, ph);
    ph = fmaf(q, -1.93530717e-3f, ph);
    return ph;
}

// ============================ WMMA kernel ============================
// One CTA (256 thr) per head h. out[h, 64j+i] = 2*sum_n [ReP*ReW^j - ImP*ImW^j]
//   P = Cd*E^i, E = exp(dtA), W = E^64 = exp(64*dtA).
// Real GEMM M=64 (i) x N=32 (j) x K=64, k-interleaved (k=2n Re, k=2n+1 Im,
// -Im folded into B). bf16 hi/lo split, 3 passes (lo*lo dropped ~2^-16):
//   acc0 = Ahi*Bhi,  acc1 = Alo*Bhi + Ahi*Blo,  out = 2*(acc0+acc1).
// Stage 1: warp0 computes Cd + E powers, warp1 computes W (direct exp) + powers.
// Stage 2: all warps generate A/B tiles (no MUFU). Stage 3: WMMA. Stage 4:
// smem-staged fully-coalesced STG.128 epilogue.

static constexpr int LDA = 72;   // bf16 elems; 144 B rows, 16B-aligned
static constexpr int LDS_O = 68; // fp32 stage stride; 272 B, 16B-aligned

__global__ __launch_bounds__(256, 5)
void s4d_wmma(const float* __restrict__ log_dt,
              const float* __restrict__ Cr,
              const float* __restrict__ logAre,
              const float* __restrict__ Aimag,
              float* __restrict__ out)
{
    __shared__ __nv_bfloat16 Ahi[64 * LDA];    // 9216 B
    __shared__ __nv_bfloat16 Alo[64 * LDA];    // 9216 B
    __shared__ __nv_bfloat16 Bhi[32 * LDA];    // 4608 B
    __shared__ __nv_bfloat16 Blo[32 * LDA];    // 4608 B
    __shared__ float2 cst[32][12];             // 3072 B
    __shared__ float  stage[32 * LDS_O];       // 8704 B  (64 x 32, ld=68)

    const int h   = blockIdx.x;
    const int tid = threadIdx.x;
    const int wid = tid >> 5;
    const int lid = tid & 31;

    // ---- stage 1: per-mode constants, split across warps 0 and 1 ----
    if (wid < 2) {
        const int n = lid;
        const float dt  = __expf(log_dt[h]);
        const float Are = -__expf(logAre[h * 32 + n]);
        const float Ai  = Aimag[h * 32 + n];
        const float dre = Are * dt;
        const float dim = Ai * dt;                  // |dim| <= ~9.8
        if (wid == 0) {
            // E = exp(dtA), Cd, E powers up to E^32
            float sn, cs;
            __sincosf(dim, &sn, &cs);
            const float e1 = __expf(dre);
            const float2 E = make_float2(e1 * cs, e1 * sn);
            const float inv = __frcp_rn(fmaf(Are, Are, Ai * Ai));
            const float ccre = Cr[(h * 32 + n) * 2 + 0];
            const float ccim = Cr[(h * 32 + n) * 2 + 1];
            const float numre = E.x - 1.0f, numim = E.y;
            const float tre = ccre * numre - ccim * numim;
            const float tim = ccre * numim + ccim * numre;
            const float2 Cd = make_float2((tre * Are + tim * Ai) * inv,
                                          (tim * Are - tre * Ai) * inv);
            const float2 E2  = cmul(E, E);
            const float2 E4  = cmul(E2, E2);
            const float2 E8  = cmul(E4, E4);
            const float2 E16 = cmul(E8, E8);
            const float2 E32 = cmul(E16, E16);
            cst[n][0] = Cd;  cst[n][1] = E;   cst[n][2] = E2;
            cst[n][3] = E4;  cst[n][4] = E8;  cst[n][5] = E16;
            cst[n][6] = E32;
        } else {
            // W = exp(64*dtA) computed directly (parallel with warp 0)
            const float ph = red2pi(dim * 64.0f);   // |dim*64| <= ~630, exact CW
            float sn, cs;
            __sincosf(ph, &sn, &cs);
            const float eT = __expf(dre * 64.0f);   // >= e^-3.2
            const float2 W   = make_float2(eT * cs, eT * sn);
            const float2 W2  = cmul(W, W);
            const float2 W4  = cmul(W2, W2);
            const float2 W8  = cmul(W4, W4);
            const float2 W16 = cmul(W8, W8);
            cst[n][7] = W;   cst[n][8] = W2;  cst[n][9] = W4;
            cst[n][10] = W8; cst[n][11] = W16;
        }
    }
    __syncthreads();

    const int n = lid;

    // ---- stage 2a: A rows i = 8*wid .. 8*wid+7 (P = Cd * E^i, hi/lo) ----
    {
        const float2 Cd  = cst[n][0];
        const float2 E   = cst[n][1];
        const float2 E2  = cst[n][2];
        const float2 E4  = cst[n][3];
        float2 base = Cd;
        if (wid & 1) base = cmul(base, cst[n][4]);   // E^8
        if (wid & 2) base = cmul(base, cst[n][5]);   // E^16
        if (wid & 4) base = cmul(base, cst[n][6]);   // E^32
        float2 z[8];
        z[0] = base;
        z[1] = cmul(base, E);
        z[2] = cmul(base, E2);
        z[4] = cmul(base, E4);
        z[3] = cmul(z[1], E2);
        z[5] = cmul(z[1], E4);
        z[6] = cmul(z[2], E4);
        z[7] = cmul(z[3], E4);
        #pragma unroll
        for (int s = 0; s < 8; s++) {
            const int i = wid * 8 + s;
            const __nv_bfloat16 rh = __float2bfloat16(z[s].x);
            const __nv_bfloat16 rl = __float2bfloat16(z[s].x - __bfloat162float(rh));
            const __nv_bfloat16 ih = __float2bfloat16(z[s].y);
            const __nv_bfloat16 il = __float2bfloat16(z[s].y - __bfloat162float(ih));
            ((__nv_bfloat162*)(Ahi + i * LDA))[n] = __nv_bfloat162(rh, ih);
            ((__nv_bfloat162*)(Alo + i * LDA))[n] = __nv_bfloat162(rl, il);
        }
    }

    // ---- stage 2b: B cols j = 4*wid .. 4*wid+3 (W^j, -Im, hi/lo) ----
    {
        const float2 W  = cst[n][7];
        const float2 W2 = cst[n][8];
        float2 base = make_float2(1.0f, 0.0f);
        if (wid & 1) base = cst[n][9];               // W^4
        if (wid & 2) base = cmul(base, cst[n][10]);  // W^8
        if (wid & 4) base = cmul(base, cst[n][11]);  // W^16
        float2 w[4];
        w[0] = base;
        w[1] = cmul(base, W);
        w[2] = cmul(base, W2);
        w[3] = cmul(w[1], W2);
        #pragma unroll
        for (int s = 0; s < 4; s++) {
            const int j = wid * 4 + s;
            const float re = w[s].x;
            const float ni = -w[s].y;
            const __nv_bfloat16 rh = __float2bfloat16(re);
            const __nv_bfloat16 rl = __float2bfloat16(re - __bfloat162float(rh));
            const __nv_bfloat16 ih = __float2bfloat16(ni);
            const __nv_bfloat16 il = __float2bfloat16(ni - __bfloat162float(ih));
            ((__nv_bfloat162*)(Bhi + j * LDA))[n] = __nv_bfloat162(rh, ih);
            ((__nv_bfloat162*)(Blo + j * LDA))[n] = __nv_bfloat162(rl, il);
        }
    }
    __syncthreads();

    // ---- stage 3: WMMA, warp tile (it = wid&3, jt = wid>>2), 2 acc chains ----
    {
        const int it = wid & 3;
        const int jt = wid >> 2;

        wmma::fragment<wmma::matrix_a, 16, 16, 16, __nv_bfloat16, wmma::row_major> ah, al;
        wmma::fragment<wmma::matrix_b, 16, 16, 16, __nv_bfloat16, wmma::col_major> bh, bl;
        wmma::fragment<wmma::accumulator, 16, 16, 16, float> acc0, acc1;
        wmma::fill_fragment(acc0, 0.0f);
        wmma::fill_fragment(acc1, 0.0f);

        #pragma unroll
        for (int kt = 0; kt < 4; kt++) {
            wmma::load_matrix_sync(ah, Ahi + (it * 16) * LDA + kt * 16, LDA);
            wmma::load_matrix_sync(bh, Bhi + (jt * 16) * LDA + kt * 16, LDA);
            wmma::mma_sync(acc0, ah, bh, acc0);
            wmma::load_matrix_sync(al, Alo + (it * 16) * LDA + kt * 16, LDA);
            wmma::mma_sync(acc1, al, bh, acc1);
            wmma::load_matrix_sync(bl, Blo + (jt * 16) * LDA + kt * 16, LDA);
            wmma::mma_sync(acc1, ah, bl, acc1);
        }
        #pragma unroll
        for (int e = 0; e < acc0.num_elements; e++)
            acc0.x[e] = 2.0f * (acc0.x[e] + acc1.x[e]);

        // element (i_local, j_local) -> stage[(it*16 + i) + (jt*16 + j)*LDS_O]
        wmma::store_matrix_sync(stage + (size_t)(jt * 16) * LDS_O + it * 16,
                                acc0, LDS_O, wmma::mem_col_major);
    }
    __syncthreads();

    // ---- stage 4: fully coalesced epilogue, 2x STG.128 per thread ----
    {
        float* op = out + (size_t)h * 2048;
        #pragma unroll
        for (int r = 0; r < 2; r++) {
            const int l = (tid + r * 256) * 4;      // 4 consecutive l, same j
            const int j = l >> 6;
            const int i = l & 63;
            const float4 v = *(const float4*)(stage + j * LDS_O + i);
            *(float4*)(op + l) = v;
        }
    }
}

// ---------------- generic fallback (any H, N2, L) ----------------
__global__ void s4d_fallback(
    const float* __restrict__ log_dt,
    const float* __restrict__ Cr,
    const float* __restrict__ logAre,
    const float* __restrict__ Aimag,
    float* __restrict__ out, int H, int N2, int L)
{
    const long long idx = (long long)blockIdx.x * blockDim.x + threadIdx.x;
    if (idx >= (long long)H * L) return;
    const int h = (int)(idx / L);
    const int l = (int)(idx % L);
    const float dt = __expf(log_dt[h]);
    const float lf = (float)l;
    float acc = 0.0f;
    for (int n = 0; n < N2; n++) {
        const float Are = -__expf(logAre[h * N2 + n]);
        const float Ai  = Aimag[h * N2 + n];
        const float dre = Are * dt;
        const float dim = Ai * dt;
        float s1, c1;
        __sincosf(dim, &s1, &c1);
        const float e1 = __expf(dre);
        const float numre = fmaf(e1, c1, -1.0f);
        const float numim = e1 * s1;
        const float inv  = __frcp_rn(fmaf(Are, Are, Ai * Ai));
        const float ccre = Cr[(h * N2 + n) * 2 + 0];
        const float ccim = Cr[(h * N2 + n) * 2 + 1];
        const float tre = ccre * numre - ccim * numim;
        const float tim = ccre * numim + ccim * numre;
        const float cdre = (tre * Are + tim * Ai) * inv;
        const float cdim = (tim * Are - tre * Ai) * inv;
        const float ph = red2pi(dim * lf);
        float s, c;
        __sincosf(ph, &s, &c);
        const float r = __expf(dre * lf);
        acc += r * (cdre * c - cdim * s);
    }
    out[idx] = 2.0f * acc;
}

extern "C" void kernel_launch(void* const* d_in, const int* in_sizes, int n_in,
                              void* d_out, int out_size)
{
    const float* log_dt = (const float*)d_in[0];
    const float* Cr     = (const float*)d_in[1];
    const float* lar    = (const float*)d_in[2];
    const float* aim    = (const float*)d_in[3];
    float* out = (float*)d_out;

    const int H  = in_sizes[0];
    const int N2 = (H > 0) ? in_sizes[2] / H : 0;
    const int L  = (H > 0) ? out_size / H : 0;

    if (N2 == 32 && L == 2048) {
        s4d_wmma<<<H, 256>>>(log_dt, Cr, lar, aim, out);
    } else {
        const long long total = (long long)H * L;
        const int blocks = (int)((total + 127) / 128);
        s4d_fallback<<<blocks, 128>>>(log_dt, Cr, lar, aim, out, H, N2, L);
    }
}

// round 7
// speedup vs baseline: 1.0573x; 1.0573x over previous
#include <cuda_runtime.h>
#include <cuda_bf16.h>
#include <mma.h>
#include <cstdint>

using namespace nvcuda;

__device__ __forceinline__ float2 cmul(float2 a, float2 b) {
    return make_float2(fmaf(a.x, b.x, -a.y * b.y), fmaf(a.x, b.y, a.y * b.x));
}

// Cody-Waite reduction to ~[-pi, pi]; exact for |ph| <~ 25000
__device__ __forceinline__ float red2pi(float ph) {
    float q = rintf(ph * 0.15915494309f);
    ph = fmaf(q, -6.28125f, ph);
    ph = fmaf(q, -1.93530717e-3f, ph);
    return ph;
}

// ============================ WMMA kernel ============================
// One CTA (128 thr, 4 warps) per head h. out[h,64j+i] = sum over modes of
// 2*Re(Cd * E^i * W^j), E = exp(dtA), W = E^64.  Real GEMM M=64 x N=32 x K=64,
// k-interleaved (k=2n Re, k=2n+1 Im, -Im folded into B). The x2 scale is
// folded into Cd. bf16 hi/lo split, dual accumulators:
//   acc0 = Ahi*Bhi,  acc1 = Alo*Bhi + Ahi*Blo   (lo*lo dropped, ~2^-16).
// Warp w owns m-tile it=w (rows 16w..16w+15) and loops jt = 0,1.
// Sized for 7 CTAs/SM: grid 1024 -> exactly one wave on 148 SMs.

static constexpr int LDA = 72;   // bf16 elems; 144 B rows, 16B-aligned

__global__ __launch_bounds__(128, 7)
void s4d_wmma(const float* __restrict__ log_dt,
              const float* __restrict__ Cr,
              const float* __restrict__ logAre,
              const float* __restrict__ Aimag,
              float* __restrict__ out)
{
    __shared__ __nv_bfloat16 Ahi[64 * LDA];    // 9216 B
    __shared__ __nv_bfloat16 Alo[64 * LDA];    // 9216 B
    __shared__ __nv_bfloat16 Bhi[32 * LDA];    // 4608 B
    __shared__ __nv_bfloat16 Blo[32 * LDA];    // 4608 B
    __shared__ float2 cst[32][12];             // 3072 B   -> 30720 B total

    const int h   = blockIdx.x;
    const int tid = threadIdx.x;
    const int wid = tid >> 5;
    const int lid = tid & 31;

    // ---- stage 1: per-mode constants, split across warps 0 and 1 ----
    if (wid < 2) {
        const int n = lid;
        const float dt  = __expf(log_dt[h]);
        const float Are = -__expf(logAre[h * 32 + n]);
        const float Ai  = Aimag[h * 32 + n];
        const float dre = Are * dt;
        const float dim = Ai * dt;                  // |dim| <= ~9.8
        if (wid == 0) {
            // E = exp(dtA), Cd (x2 folded in), E powers up to E^32
            float sn, cs;
            __sincosf(dim, &sn, &cs);
            const float e1 = __expf(dre);
            const float2 E = make_float2(e1 * cs, e1 * sn);
            const float inv = __frcp_rn(fmaf(Are, Are, Ai * Ai));
            const float ccre = Cr[(h * 32 + n) * 2 + 0];
            const float ccim = Cr[(h * 32 + n) * 2 + 1];
            const float numre = E.x - 1.0f, numim = E.y;
            const float tre = ccre * numre - ccim * numim;
            const float tim = ccre * numim + ccim * numre;
            const float2 Cd = make_float2(2.0f * (tre * Are + tim * Ai) * inv,
                                          2.0f * (tim * Are - tre * Ai) * inv);
            const float2 E2  = cmul(E, E);
            const float2 E4  = cmul(E2, E2);
            const float2 E8  = cmul(E4, E4);
            const float2 E16 = cmul(E8, E8);
            const float2 E32 = cmul(E16, E16);
            cst[n][0] = Cd;  cst[n][1] = E;   cst[n][2] = E2;
            cst[n][3] = E4;  cst[n][4] = E8;  cst[n][5] = E16;
            cst[n][6] = E32;
        } else {
            // W = exp(64*dtA) computed directly (parallel with warp 0)
            const float ph = red2pi(dim * 64.0f);   // |ph_arg| <= ~630, exact CW
            float sn, cs;
            __sincosf(ph, &sn, &cs);
            const float eT = __expf(dre * 64.0f);   // >= e^-3.2
            const float2 W   = make_float2(eT * cs, eT * sn);
            const float2 W2  = cmul(W, W);
            const float2 W4  = cmul(W2, W2);
            const float2 W8  = cmul(W4, W4);
            const float2 W16 = cmul(W8, W8);
            cst[n][7] = W;   cst[n][8] = W2;  cst[n][9] = W4;
            cst[n][10] = W8; cst[n][11] = W16;
        }
    }
    __syncthreads();

    const int n = lid;

    // ---- stage 2a: A rows i = 16*wid .. 16*wid+15 (2*Cd * E^i, hi/lo) ----
    {
        const float2 E   = cst[n][1];
        const float2 E2  = cst[n][2];
        const float2 E4  = cst[n][3];
        const float2 E8  = cst[n][4];
        float2 base = cst[n][0];                     // 2*Cd
        if (wid & 1) base = cmul(base, cst[n][5]);   // E^16
        if (wid & 2) base = cmul(base, cst[n][6]);   // E^32
        float2 z[16];
        z[0] = base;
        z[1] = cmul(base, E);
        z[2] = cmul(base, E2);
        z[4] = cmul(base, E4);
        z[3] = cmul(z[1], E2);
        z[5] = cmul(z[1], E4);
        z[6] = cmul(z[2], E4);
        z[7] = cmul(z[3], E4);
        #pragma unroll
        for (int s = 0; s < 8; s++) z[8 + s] = cmul(z[s], E8);
        #pragma unroll
        for (int s = 0; s < 16; s++) {
            const int i = wid * 16 + s;
            const __nv_bfloat16 rh = __float2bfloat16(z[s].x);
            const __nv_bfloat16 rl = __float2bfloat16(z[s].x - __bfloat162float(rh));
            const __nv_bfloat16 ih = __float2bfloat16(z[s].y);
            const __nv_bfloat16 il = __float2bfloat16(z[s].y - __bfloat162float(ih));
            ((__nv_bfloat162*)(Ahi + i * LDA))[n] = __nv_bfloat162(rh, ih);
            ((__nv_bfloat162*)(Alo + i * LDA))[n] = __nv_bfloat162(rl, il);
        }
    }

    // ---- stage 2b: B cols j = 8*wid .. 8*wid+7 (W^j, -Im, hi/lo) ----
    {
        const float2 W  = cst[n][7];
        const float2 W2 = cst[n][8];
        const float2 W4 = cst[n][9];
        float2 base = make_float2(1.0f, 0.0f);
        if (wid & 1) base = cst[n][10];              // W^8
        if (wid & 2) base = cmul(base, cst[n][11]);  // W^16
        float2 w[8];
        w[0] = base;
        w[1] = cmul(base, W);
        w[2] = cmul(base, W2);
        w[4] = cmul(base, W4);
        w[3] = cmul(w[1], W2);
        w[5] = cmul(w[1], W4);
        w[6] = cmul(w[2], W4);
        w[7] = cmul(w[3], W4);
        #pragma unroll
        for (int s = 0; s < 8; s++) {
            const int j = wid * 8 + s;
            const float re = w[s].x;
            const float ni = -w[s].y;
            const __nv_bfloat16 rh = __float2bfloat16(re);
            const __nv_bfloat16 rl = __float2bfloat16(re - __bfloat162float(rh));
            const __nv_bfloat16 ih = __float2bfloat16(ni);
            const __nv_bfloat16 il = __float2bfloat16(ni - __bfloat162float(ih));
            ((__nv_bfloat162*)(Bhi + j * LDA))[n] = __nv_bfloat162(rh, ih);
            ((__nv_bfloat162*)(Blo + j * LDA))[n] = __nv_bfloat162(rl, il);
        }
    }
    __syncthreads();

    // ---- stage 3: WMMA. Warp it=wid, loop jt = 0,1; dual accumulators ----
    {
        const int it = wid;
        #pragma unroll
        for (int jt = 0; jt < 2; jt++) {
            wmma::fragment<wmma::matrix_a, 16, 16, 16, __nv_bfloat16, wmma::row_major> ah, al;
            wmma::fragment<wmma::matrix_b, 16, 16, 16, __nv_bfloat16, wmma::col_major> bh, bl;
            wmma::fragment<wmma::accumulator, 16, 16, 16, float> acc0, acc1;
            wmma::fill_fragment(acc0, 0.0f);
            wmma::fill_fragment(acc1, 0.0f);

            #pragma unroll
            for (int kt = 0; kt < 4; kt++) {
                wmma::load_matrix_sync(ah, Ahi + (it * 16) * LDA + kt * 16, LDA);
                wmma::load_matrix_sync(bh, Bhi + (jt * 16) * LDA + kt * 16, LDA);
                wmma::mma_sync(acc0, ah, bh, acc0);
                wmma::load_matrix_sync(al, Alo + (it * 16) * LDA + kt * 16, LDA);
                wmma::mma_sync(acc1, al, bh, acc1);
                wmma::load_matrix_sync(bl, Blo + (jt * 16) * LDA + kt * 16, LDA);
                wmma::mma_sync(acc1, ah, bl, acc1);
            }
            #pragma unroll
            for (int e = 0; e < acc0.num_elements; e++) acc0.x[e] += acc1.x[e];

            // out element (i, j) at out[h*2048 + j*64 + i] -> col-major, ld 64
            float* op = out + (size_t)h * 2048 + (size_t)(jt * 16) * 64 + it * 16;
            wmma::store_matrix_sync(op, acc0, 64, wmma::mem_col_major);
        }
    }
}

// ---------------- generic fallback (any H, N2, L) ----------------
__global__ void s4d_fallback(
    const float* __restrict__ log_dt,
    const float* __restrict__ Cr,
    const float* __restrict__ logAre,
    const float* __restrict__ Aimag,
    float* __restrict__ out, int H, int N2, int L)
{
    const long long idx = (long long)blockIdx.x * blockDim.x + threadIdx.x;
    if (idx >= (long long)H * L) return;
    const int h = (int)(idx / L);
    const int l = (int)(idx % L);
    const float dt = __expf(log_dt[h]);
    const float lf = (float)l;
    float acc = 0.0f;
    for (int n = 0; n < N2; n++) {
        const float Are = -__expf(logAre[h * N2 + n]);
        const float Ai  = Aimag[h * N2 + n];
        const float dre = Are * dt;
        const float dim = Ai * dt;
        float s1, c1;
        __sincosf(dim, &s1, &c1);
        const float e1 = __expf(dre);
        const float numre = fmaf(e1, c1, -1.0f);
        const float numim = e1 * s1;
        const float inv  = __frcp_rn(fmaf(Are, Are, Ai * Ai));
        const float ccre = Cr[(h * N2 + n) * 2 + 0];
        const float ccim = Cr[(h * N2 + n) * 2 + 1];
        const float tre = ccre * numre - ccim * numim;
        const float tim = ccre * numim + ccim * numre;
        const float cdre = (tre * Are + tim * Ai) * inv;
        const float cdim = (tim * Are - tre * Ai) * inv;
        const float ph = red2pi(dim * lf);
        float s, c;
        __sincosf(ph, &s, &c);
        const float r = __expf(dre * lf);
        acc += r * (cdre * c - cdim * s);
    }
    out[idx] = 2.0f * acc;
}

extern "C" void kernel_launch(void* const* d_in, const int* in_sizes, int n_in,
                              void* d_out, int out_size)
{
    const float* log_dt = (const float*)d_in[0];
    const float* Cr     = (const float*)d_in[1];
    const float* lar    = (const float*)d_in[2];
    const float* aim    = (const float*)d_in[3];
    float* out = (float*)d_out;

    const int H  = in_sizes[0];
    const int N2 = (H > 0) ? in_sizes[2] / H : 0;
    const int L  = (H > 0) ? out_size / H : 0;

    if (N2 == 32 && L == 2048) {
        s4d_wmma<<<H, 128>>>(log_dt, Cr, lar, aim, out);
    } else {
        const long long total = (long long)H * L;
        const int blocks = (int)((total + 127) / 128);
        s4d_fallback<<<blocks, 128>>>(log_dt, Cr, lar, aim, out, H, N2, L);
    }
}

// round 8
// speedup vs baseline: 1.1469x; 1.0847x over previous
#include <cuda_runtime.h>
#include <cuda_bf16.h>
#include <mma.h>
#include <cstdint>

using namespace nvcuda;

__device__ __forceinline__ float2 cmul(float2 a, float2 b) {
    return make_float2(fmaf(a.x, b.x, -a.y * b.y), fmaf(a.x, b.y, a.y * b.x));
}

// Cody-Waite reduction to ~[-pi, pi]; exact for |ph| <~ 25000
__device__ __forceinline__ float red2pi(float ph) {
    float q = rintf(ph * 0.15915494309f);
    ph = fmaf(q, -6.28125f, ph);
    ph = fmaf(q, -1.93530717e-3f, ph);
    return ph;
}

// Pack (lo = x, hi = y) into one bf16x2 with a single cvt instruction.
// PTX: cvt.rn.bf16x2.f32 d, a, b  ->  d.hi = bf16(a), d.lo = bf16(b)
__device__ __forceinline__ uint32_t pack_bf16x2(float x_lo, float y_hi) {
    uint32_t r;
    asm("cvt.rn.bf16x2.f32 %0, %1, %2;" : "=r"(r) : "f"(y_hi), "f"(x_lo));
    return r;
}

// Write hi/lo split of complex z as two packed bf16x2 words.
__device__ __forceinline__ void split_store(__nv_bfloat16* hiArr, __nv_bfloat16* loArr,
                                            int row, int lda, int n, float2 z) {
    const uint32_t ph = pack_bf16x2(z.x, z.y);
    const float fx = __uint_as_float(ph << 16);           // bf16(z.x) as f32
    const float fy = __uint_as_float(ph & 0xFFFF0000u);   // bf16(z.y) as f32
    const uint32_t pl = pack_bf16x2(z.x - fx, z.y - fy);
    ((uint32_t*)(hiArr + row * lda))[n] = ph;
    ((uint32_t*)(loArr + row * lda))[n] = pl;
}

// ============================ WMMA kernel ============================
// One CTA (128 thr, 4 warps) per head h. out[h,64j+i] = sum over modes of
// 2*Re(Cd * E^i * W^j), E = exp(dtA), W = E^64.  Real GEMM M=64 x N=32 x K=64,
// k-interleaved (k=2n Re, k=2n+1 Im, -Im folded into B), x2 folded into Cd.
// bf16 hi/lo split, dual accumulators:
//   acc0 = Ahi*Bhi,  acc1 = Alo*Bhi + Ahi*Blo   (lo*lo dropped, ~2^-16).
// Warp w owns m-tile it=w and loops jt = 0,1. 7 CTAs/SM -> exactly one wave.

static constexpr int LDA = 72;   // bf16 elems; 144 B rows, 16B-aligned

__global__ __launch_bounds__(128, 7)
void s4d_wmma(const float* __restrict__ log_dt,
              const float* __restrict__ Cr,
              const float* __restrict__ logAre,
              const float* __restrict__ Aimag,
              float* __restrict__ out)
{
    __shared__ __nv_bfloat16 Ahi[64 * LDA];    // 9216 B
    __shared__ __nv_bfloat16 Alo[64 * LDA];    // 9216 B
    __shared__ __nv_bfloat16 Bhi[32 * LDA];    // 4608 B
    __shared__ __nv_bfloat16 Blo[32 * LDA];    // 4608 B
    __shared__ float2 cst[32][12];             // 3072 B   -> 30720 B total

    const int h   = blockIdx.x;
    const int tid = threadIdx.x;
    const int wid = tid >> 5;
    const int lid = tid & 31;

    // ---- stage 1: per-mode constants, split across warps 0 and 1 ----
    if (wid < 2) {
        const int n = lid;
        const float dt  = __expf(log_dt[h]);
        const float Are = -__expf(logAre[h * 32 + n]);
        const float Ai  = Aimag[h * 32 + n];
        const float dre = Are * dt;
        const float dim = Ai * dt;                  // |dim| <= ~9.8
        if (wid == 0) {
            // E = exp(dtA), Cd (x2 folded in), E powers up to E^32
            float sn, cs;
            __sincosf(dim, &sn, &cs);
            const float e1 = __expf(dre);
            const float2 E = make_float2(e1 * cs, e1 * sn);
            const float inv = __frcp_rn(fmaf(Are, Are, Ai * Ai));
            const float ccre = Cr[(h * 32 + n) * 2 + 0];
            const float ccim = Cr[(h * 32 + n) * 2 + 1];
            const float numre = E.x - 1.0f, numim = E.y;
            const float tre = ccre * numre - ccim * numim;
            const float tim = ccre * numim + ccim * numre;
            const float2 Cd = make_float2(2.0f * (tre * Are + tim * Ai) * inv,
                                          2.0f * (tim * Are - tre * Ai) * inv);
            const float2 E2  = cmul(E, E);
            const float2 E4  = cmul(E2, E2);
            const float2 E8  = cmul(E4, E4);
            const float2 E16 = cmul(E8, E8);
            const float2 E32 = cmul(E16, E16);
            cst[n][0] = Cd;  cst[n][1] = E;   cst[n][2] = E2;
            cst[n][3] = E4;  cst[n][4] = E8;  cst[n][5] = E16;
            cst[n][6] = E32;
        } else {
            // W = exp(64*dtA) computed directly (parallel with warp 0)
            const float ph = red2pi(dim * 64.0f);   // |arg| <= ~630, exact CW
            float sn, cs;
            __sincosf(ph, &sn, &cs);
            const float eT = __expf(dre * 64.0f);   // >= e^-3.2
            const float2 W   = make_float2(eT * cs, eT * sn);
            const float2 W2  = cmul(W, W);
            const float2 W4  = cmul(W2, W2);
            const float2 W8  = cmul(W4, W4);
            const float2 W16 = cmul(W8, W8);
            cst[n][7] = W;   cst[n][8] = W2;  cst[n][9] = W4;
            cst[n][10] = W8; cst[n][11] = W16;
        }
    }
    __syncthreads();

    const int n = lid;

    // ---- stage 2a: A rows i = 16*wid .. 16*wid+15 (2*Cd * E^i, hi/lo) ----
    {
        const float2 E   = cst[n][1];
        const float2 E2  = cst[n][2];
        const float2 E4  = cst[n][3];
        const float2 E8  = cst[n][4];
        float2 base = cst[n][0];                     // 2*Cd
        if (wid & 1) base = cmul(base, cst[n][5]);   // E^16
        if (wid & 2) base = cmul(base, cst[n][6]);   // E^32
        float2 z[16];
        z[0] = base;
        z[1] = cmul(base, E);
        z[2] = cmul(base, E2);
        z[4] = cmul(base, E4);
        z[3] = cmul(z[1], E2);
        z[5] = cmul(z[1], E4);
        z[6] = cmul(z[2], E4);
        z[7] = cmul(z[3], E4);
        #pragma unroll
        for (int s = 0; s < 8; s++) z[8 + s] = cmul(z[s], E8);
        #pragma unroll
        for (int s = 0; s < 16; s++)
            split_store(Ahi, Alo, wid * 16 + s, LDA, n, z[s]);
    }

    // ---- stage 2b: B cols j = 8*wid .. 8*wid+7 (W^j, -Im, hi/lo) ----
    {
        const float2 W  = cst[n][7];
        const float2 W2 = cst[n][8];
        const float2 W4 = cst[n][9];
        float2 base = make_float2(1.0f, 0.0f);
        if (wid & 1) base = cst[n][10];              // W^8
        if (wid & 2) base = cmul(base, cst[n][11]);  // W^16
        float2 w[8];
        w[0] = base;
        w[1] = cmul(base, W);
        w[2] = cmul(base, W2);
        w[4] = cmul(base, W4);
        w[3] = cmul(w[1], W2);
        w[5] = cmul(w[1], W4);
        w[6] = cmul(w[2], W4);
        w[7] = cmul(w[3], W4);
        #pragma unroll
        for (int s = 0; s < 8; s++) {
            const float2 bw = make_float2(w[s].x, -w[s].y);  // -Im on B side
            split_store(Bhi, Blo, wid * 8 + s, LDA, n, bw);
        }
    }
    __syncthreads();

    // ---- stage 3: WMMA. Warp it=wid, loop jt = 0,1; dual accumulators ----
    {
        const int it = wid;
        #pragma unroll
        for (int jt = 0; jt < 2; jt++) {
            wmma::fragment<wmma::matrix_a, 16, 16, 16, __nv_bfloat16, wmma::row_major> ah, al;
            wmma::fragment<wmma::matrix_b, 16, 16, 16, __nv_bfloat16, wmma::col_major> bh, bl;
            wmma::fragment<wmma::accumulator, 16, 16, 16, float> acc0, acc1;
            wmma::fill_fragment(acc0, 0.0f);
            wmma::fill_fragment(acc1, 0.0f);

            #pragma unroll
            for (int kt = 0; kt < 4; kt++) {
                wmma::load_matrix_sync(ah, Ahi + (it * 16) * LDA + kt * 16, LDA);
                wmma::load_matrix_sync(bh, Bhi + (jt * 16) * LDA + kt * 16, LDA);
                wmma::mma_sync(acc0, ah, bh, acc0);
                wmma::load_matrix_sync(al, Alo + (it * 16) * LDA + kt * 16, LDA);
                wmma::mma_sync(acc1, al, bh, acc1);
                wmma::load_matrix_sync(bl, Blo + (jt * 16) * LDA + kt * 16, LDA);
                wmma::mma_sync(acc1, ah, bl, acc1);
            }
            #pragma unroll
            for (int e = 0; e < acc0.num_elements; e++) acc0.x[e] += acc1.x[e];

            // out element (i, j) at out[h*2048 + j*64 + i] -> col-major, ld 64
            float* op = out + (size_t)h * 2048 + (size_t)(jt * 16) * 64 + it * 16;
            wmma::store_matrix_sync(op, acc0, 64, wmma::mem_col_major);
        }
    }
}

// ---------------- generic fallback (any H, N2, L) ----------------
__global__ void s4d_fallback(
    const float* __restrict__ log_dt,
    const float* __restrict__ Cr,
    const float* __restrict__ logAre,
    const float* __restrict__ Aimag,
    float* __restrict__ out, int H, int N2, int L)
{
    const long long idx = (long long)blockIdx.x * blockDim.x + threadIdx.x;
    if (idx >= (long long)H * L) return;
    const int h = (int)(idx / L);
    const int l = (int)(idx % L);
    const float dt = __expf(log_dt[h]);
    const float lf = (float)l;
    float acc = 0.0f;
    for (int n = 0; n < N2; n++) {
        const float Are = -__expf(logAre[h * N2 + n]);
        const float Ai  = Aimag[h * N2 + n];
        const float dre = Are * dt;
        const float dim = Ai * dt;
        float s1, c1;
        __sincosf(dim, &s1, &c1);
        const float e1 = __expf(dre);
        const float numre = fmaf(e1, c1, -1.0f);
        const float numim = e1 * s1;
        const float inv  = __frcp_rn(fmaf(Are, Are, Ai * Ai));
        const float ccre = Cr[(h * N2 + n) * 2 + 0];
        const float ccim = Cr[(h * N2 + n) * 2 + 1];
        const float tre = ccre * numre - ccim * numim;
        const float tim = ccre * numim + ccim * numre;
        const float cdre = (tre * Are + tim * Ai) * inv;
        const float cdim = (tim * Are - tre * Ai) * inv;
        const float ph = red2pi(dim * lf);
        float s, c;
        __sincosf(ph, &s, &c);
        const float r = __expf(dre * lf);
        acc += r * (cdre * c - cdim * s);
    }
    out[idx] = 2.0f * acc;
}

extern "C" void kernel_launch(void* const* d_in, const int* in_sizes, int n_in,
                              void* d_out, int out_size)
{
    const float* log_dt = (const float*)d_in[0];
    const float* Cr     = (const float*)d_in[1];
    const float* lar    = (const float*)d_in[2];
    const float* aim    = (const float*)d_in[3];
    float* out = (float*)d_out;

    const int H  = in_sizes[0];
    const int N2 = (H > 0) ? in_sizes[2] / H : 0;
    const int L  = (H > 0) ? out_size / H : 0;

    if (N2 == 32 && L == 2048) {
        s4d_wmma<<<H, 128>>>(log_dt, Cr, lar, aim, out);
    } else {
        const long long total = (long long)H * L;
        const int blocks = (int)((total + 127) / 128);
        s4d_fallback<<<blocks, 128>>>(log_dt, Cr, lar, aim, out, H, N2, L);
    }
}

// round 9
// speedup vs baseline: 1.2688x; 1.1063x over previous
#include <cuda_runtime.h>
#include <cuda_fp16.h>
#include <mma.h>
#include <cstdint>

using namespace nvcuda;

__device__ __forceinline__ float2 cmul(float2 a, float2 b) {
    return make_float2(fmaf(a.x, b.x, -a.y * b.y), fmaf(a.x, b.y, a.y * b.x));
}

// Cody-Waite reduction to ~[-pi, pi]; exact for |ph| <~ 25000
__device__ __forceinline__ float red2pi(float ph) {
    float q = rintf(ph * 0.15915494309f);
    ph = fmaf(q, -6.28125f, ph);
    ph = fmaf(q, -1.93530717e-3f, ph);
    return ph;
}

// ============================ WMMA kernel ============================
// One CTA (128 thr, 4 warps) per head h. out[h,64j+i] = sum over modes of
// 2*Re(Cd * E^i * W^j), E = exp(dtA), W = E^64.  Real GEMM M=64 x N=32 x K=64,
// k-interleaved (k=2n Re, k=2n+1 Im); B holds powers of conj(W) so no sign
// fixup is needed; the x2 is folded into Cd.
// fp16 asymmetric split: A = Ahi + Alo (exact to 2^-22), B rounded once
// (error 2^-12 rms). Two passes: acc = Ahi*B + Alo*B.
// Warp w owns m-tile it=w; A fragments hoisted across the jt loop.
// 7 CTAs/SM -> grid 1024 runs in exactly one wave on 148 SMs.

static constexpr int LDA = 72;   // fp16 elems; 144 B rows, 16B-aligned

__global__ __launch_bounds__(128, 7)
void s4d_wmma(const float* __restrict__ log_dt,
              const float* __restrict__ Cr,
              const float* __restrict__ logAre,
              const float* __restrict__ Aimag,
              float* __restrict__ out)
{
    __shared__ __half Ahi[64 * LDA];    // 9216 B
    __shared__ __half Alo[64 * LDA];    // 9216 B
    __shared__ __half Bm [32 * LDA];    // 4608 B
    __shared__ float2 cst[32][12];      // 3072 B   -> 26112 B total

    const int h   = blockIdx.x;
    const int tid = threadIdx.x;
    const int wid = tid >> 5;
    const int lid = tid & 31;

    // ---- stage 1: per-mode constants, split across warps 0 and 1 ----
    if (wid < 2) {
        const int n = lid;
        const float dt  = __expf(log_dt[h]);
        const float Are = -__expf(logAre[h * 32 + n]);
        const float Ai  = Aimag[h * 32 + n];
        const float dre = Are * dt;
        const float dim = Ai * dt;                  // |dim| <= ~9.8
        if (wid == 0) {
            // E = exp(dtA), Cd (x2 folded in), E powers up to E^32
            float sn, cs;
            __sincosf(dim, &sn, &cs);
            const float e1 = __expf(dre);
            const float2 E = make_float2(e1 * cs, e1 * sn);
            const float inv = __frcp_rn(fmaf(Are, Are, Ai * Ai));
            const float ccre = Cr[(h * 32 + n) * 2 + 0];
            const float ccim = Cr[(h * 32 + n) * 2 + 1];
            const float numre = E.x - 1.0f, numim = E.y;
            const float tre = ccre * numre - ccim * numim;
            const float tim = ccre * numim + ccim * numre;
            const float2 Cd = make_float2(2.0f * (tre * Are + tim * Ai) * inv,
                                          2.0f * (tim * Are - tre * Ai) * inv);
            const float2 E2  = cmul(E, E);
            const float2 E4  = cmul(E2, E2);
            const float2 E8  = cmul(E4, E4);
            const float2 E16 = cmul(E8, E8);
            const float2 E32 = cmul(E16, E16);
            cst[n][0] = Cd;  cst[n][1] = E;   cst[n][2] = E2;
            cst[n][3] = E4;  cst[n][4] = E8;  cst[n][5] = E16;
            cst[n][6] = E32;
        } else {
            // Wc = conj(exp(64*dtA)) computed directly (parallel with warp 0)
            const float ph = red2pi(dim * 64.0f);   // |arg| <= ~630, exact CW
            float sn, cs;
            __sincosf(ph, &sn, &cs);
            const float eT = __expf(dre * 64.0f);   // >= e^-3.2
            const float2 Wc   = make_float2(eT * cs, -eT * sn);   // conj(W)
            const float2 Wc2  = cmul(Wc, Wc);
            const float2 Wc4  = cmul(Wc2, Wc2);
            const float2 Wc8  = cmul(Wc4, Wc4);
            const float2 Wc16 = cmul(Wc8, Wc8);
            cst[n][7] = Wc;   cst[n][8] = Wc2;  cst[n][9] = Wc4;
            cst[n][10] = Wc8; cst[n][11] = Wc16;
        }
    }
    __syncthreads();

    const int n = lid;

    // ---- stage 2a: A rows i = 16*wid .. 16*wid+15 (2*Cd * E^i, hi/lo fp16) ----
    {
        const float2 E   = cst[n][1];
        const float2 E2  = cst[n][2];
        const float2 E4  = cst[n][3];
        const float2 E8  = cst[n][4];
        float2 base = cst[n][0];                     // 2*Cd
        if (wid & 1) base = cmul(base, cst[n][5]);   // E^16
        if (wid & 2) base = cmul(base, cst[n][6]);   // E^32
        float2 z[16];
        z[0] = base;
        z[1] = cmul(base, E);
        z[2] = cmul(base, E2);
        z[4] = cmul(base, E4);
        z[3] = cmul(z[1], E2);
        z[5] = cmul(z[1], E4);
        z[6] = cmul(z[2], E4);
        z[7] = cmul(z[3], E4);
        #pragma unroll
        for (int s = 0; s < 8; s++) z[8 + s] = cmul(z[s], E8);
        #pragma unroll
        for (int s = 0; s < 16; s++) {
            const int i = wid * 16 + s;
            const __half2 hi = __floats2half2_rn(z[s].x, z[s].y);
            const float2 bk = __half22float2(hi);
            const __half2 lo = __floats2half2_rn(z[s].x - bk.x, z[s].y - bk.y);
            ((__half2*)(Ahi + i * LDA))[n] = hi;
            ((__half2*)(Alo + i * LDA))[n] = lo;
        }
    }

    // ---- stage 2b: B cols j = 8*wid .. 8*wid+7 (conj(W)^j, fp16 single) ----
    {
        const float2 W  = cst[n][7];
        const float2 W2 = cst[n][8];
        const float2 W4 = cst[n][9];
        float2 base = make_float2(1.0f, 0.0f);
        if (wid & 1) base = cst[n][10];              // Wc^8
        if (wid & 2) base = cmul(base, cst[n][11]);  // Wc^16
        float2 w[8];
        w[0] = base;
        w[1] = cmul(base, W);
        w[2] = cmul(base, W2);
        w[4] = cmul(base, W4);
        w[3] = cmul(w[1], W2);
        w[5] = cmul(w[1], W4);
        w[6] = cmul(w[2], W4);
        w[7] = cmul(w[3], W4);
        #pragma unroll
        for (int s = 0; s < 8; s++) {
            const int j = wid * 8 + s;
            ((__half2*)(Bm + j * LDA))[n] = __floats2half2_rn(w[s].x, w[s].y);
        }
    }
    __syncthreads();

    // ---- stage 3: WMMA. A fragments hoisted; 2 passes (Ahi*B + Alo*B) ----
    {
        const int it = wid;
        wmma::fragment<wmma::matrix_a, 16, 16, 16, __half, wmma::row_major> ah[4], al[4];
        #pragma unroll
        for (int kt = 0; kt < 4; kt++) {
            wmma::load_matrix_sync(ah[kt], Ahi + (it * 16) * LDA + kt * 16, LDA);
            wmma::load_matrix_sync(al[kt], Alo + (it * 16) * LDA + kt * 16, LDA);
        }
        #pragma unroll
        for (int jt = 0; jt < 2; jt++) {
            wmma::fragment<wmma::matrix_b, 16, 16, 16, __half, wmma::col_major> bf;
            wmma::fragment<wmma::accumulator, 16, 16, 16, float> acc0, acc1;
            wmma::fill_fragment(acc0, 0.0f);
            wmma::fill_fragment(acc1, 0.0f);
            #pragma unroll
            for (int kt = 0; kt < 4; kt++) {
                wmma::load_matrix_sync(bf, Bm + (jt * 16) * LDA + kt * 16, LDA);
                wmma::mma_sync(acc0, ah[kt], bf, acc0);
                wmma::mma_sync(acc1, al[kt], bf, acc1);
            }
            #pragma unroll
            for (int e = 0; e < acc0.num_elements; e++) acc0.x[e] += acc1.x[e];

            // out element (i, j) at out[h*2048 + j*64 + i] -> col-major, ld 64
            float* op = out + (size_t)h * 2048 + (size_t)(jt * 16) * 64 + it * 16;
            wmma::store_matrix_sync(op, acc0, 64, wmma::mem_col_major);
        }
    }
}

// ---------------- generic fallback (any H, N2, L) ----------------
__global__ void s4d_fallback(
    const float* __restrict__ log_dt,
    const float* __restrict__ Cr,
    const float* __restrict__ logAre,
    const float* __restrict__ Aimag,
    float* __restrict__ out, int H, int N2, int L)
{
    const long long idx = (long long)blockIdx.x * blockDim.x + threadIdx.x;
    if (idx >= (long long)H * L) return;
    const int h = (int)(idx / L);
    const int l = (int)(idx % L);
    const float dt = __expf(log_dt[h]);
    const float lf = (float)l;
    float acc = 0.0f;
    for (int n = 0; n < N2; n++) {
        const float Are = -__expf(logAre[h * N2 + n]);
        const float Ai  = Aimag[h * N2 + n];
        const float dre = Are * dt;
        const float dim = Ai * dt;
        float s1, c1;
        __sincosf(dim, &s1, &c1);
        const float e1 = __expf(dre);
        const float numre = fmaf(e1, c1, -1.0f);
        const float numim = e1 * s1;
        const float inv  = __frcp_rn(fmaf(Are, Are, Ai * Ai));
        const float ccre = Cr[(h * N2 + n) * 2 + 0];
        const float ccim = Cr[(h * N2 + n) * 2 + 1];
        const float tre = ccre * numre - ccim * numim;
        const float tim = ccre * numim + ccim * numre;
        const float cdre = (tre * Are + tim * Ai) * inv;
        const float cdim = (tim * Are - tre * Ai) * inv;
        const float ph = red2pi(dim * lf);
        float s, c;
        __sincosf(ph, &s, &c);
        const float r = __expf(dre * lf);
        acc += r * (cdre * c - cdim * s);
    }
    out[idx] = 2.0f * acc;
}

extern "C" void kernel_launch(void* const* d_in, const int* in_sizes, int n_in,
                              void* d_out, int out_size)
{
    const float* log_dt = (const float*)d_in[0];
    const float* Cr     = (const float*)d_in[1];
    const float* lar    = (const float*)d_in[2];
    const float* aim    = (const float*)d_in[3];
    float* out = (float*)d_out;

    const int H  = in_sizes[0];
    const int N2 = (H > 0) ? in_sizes[2] / H : 0;
    const int L  = (H > 0) ? out_size / H : 0;

    if (N2 == 32 && L == 2048) {
        s4d_wmma<<<H, 128>>>(log_dt, Cr, lar, aim, out);
    } else {
        const long long total = (long long)H * L;
        const int blocks = (int)((total + 127) / 128);
        s4d_fallback<<<blocks, 128>>>(log_dt, Cr, lar, aim, out, H, N2, L);
    }
}

// round 10
// speedup vs baseline: 1.5859x; 1.2500x over previous
#include <cuda_runtime.h>
#include <cuda_fp16.h>
#include <mma.h>
#include <cstdint>

using namespace nvcuda;

__device__ __forceinline__ float2 cmul(float2 a, float2 b) {
    return make_float2(fmaf(a.x, b.x, -a.y * b.y), fmaf(a.x, b.y, a.y * b.x));
}

// Cody-Waite reduction to ~[-pi, pi]; exact for |ph| <~ 25000
__device__ __forceinline__ float red2pi(float ph) {
    float q = rintf(ph * 0.15915494309f);
    ph = fmaf(q, -6.28125f, ph);
    ph = fmaf(q, -1.93530717e-3f, ph);
    return ph;
}

// ============================ WMMA kernel ============================
// One CTA (128 thr, 4 warps) per head h. out[h,64j+i] = sum over modes of
// 2*Re(Cd * E^i * W^j), E = exp(dtA), W = E^64.  Real GEMM M=64 x N=32 x K=64,
// k-interleaved (k=2n Re, k=2n+1 Im); B holds powers of conj(W) (so no sign
// fixup); the x2 is folded into Cd.  SINGLE-PASS fp16: both A and B rounded
// once (each ~2^-12 relative; measured B-only error was 9.9e-5, combined
// estimate ~1.5e-4, comfortably under the 1e-3 gate).
// Warp w owns m-tile it=w; A fragments hoisted across the jt loop.
// 7 CTAs/SM -> grid 1024 runs in exactly one wave on 148 SMs.

static constexpr int LDA = 72;   // fp16 elems; 144 B rows, 16B-aligned

__global__ __launch_bounds__(128, 7)
void s4d_wmma(const float* __restrict__ log_dt,
              const float* __restrict__ Cr,
              const float* __restrict__ logAre,
              const float* __restrict__ Aimag,
              float* __restrict__ out)
{
    __shared__ __half Am[64 * LDA];     // 9216 B
    __shared__ __half Bm[32 * LDA];     // 4608 B
    __shared__ float2 cst[32][12];      // 3072 B   -> 16896 B total

    const int h   = blockIdx.x;
    const int tid = threadIdx.x;
    const int wid = tid >> 5;
    const int lid = tid & 31;

    // ---- stage 1: per-mode constants, split across warps 0 and 1 ----
    if (wid < 2) {
        const int n = lid;
        const float dt  = __expf(log_dt[h]);
        const float Are = -__expf(logAre[h * 32 + n]);
        const float Ai  = Aimag[h * 32 + n];
        const float dre = Are * dt;
        const float dim = Ai * dt;                  // |dim| <= ~9.8
        if (wid == 0) {
            // E = exp(dtA), Cd (x2 folded in), E powers up to E^32
            float sn, cs;
            __sincosf(dim, &sn, &cs);
            const float e1 = __expf(dre);
            const float2 E = make_float2(e1 * cs, e1 * sn);
            const float inv = __frcp_rn(fmaf(Are, Are, Ai * Ai));
            const float ccre = Cr[(h * 32 + n) * 2 + 0];
            const float ccim = Cr[(h * 32 + n) * 2 + 1];
            const float numre = E.x - 1.0f, numim = E.y;
            const float tre = ccre * numre - ccim * numim;
            const float tim = ccre * numim + ccim * numre;
            const float2 Cd = make_float2(2.0f * (tre * Are + tim * Ai) * inv,
                                          2.0f * (tim * Are - tre * Ai) * inv);
            const float2 E2  = cmul(E, E);
            const float2 E4  = cmul(E2, E2);
            const float2 E8  = cmul(E4, E4);
            const float2 E16 = cmul(E8, E8);
            const float2 E32 = cmul(E16, E16);
            cst[n][0] = Cd;  cst[n][1] = E;   cst[n][2] = E2;
            cst[n][3] = E4;  cst[n][4] = E8;  cst[n][5] = E16;
            cst[n][6] = E32;
        } else {
            // Wc = conj(exp(64*dtA)) computed directly (parallel with warp 0)
            const float ph = red2pi(dim * 64.0f);   // |arg| <= ~630, exact CW
            float sn, cs;
            __sincosf(ph, &sn, &cs);
            const float eT = __expf(dre * 64.0f);   // >= e^-3.2
            const float2 Wc   = make_float2(eT * cs, -eT * sn);   // conj(W)
            const float2 Wc2  = cmul(Wc, Wc);
            const float2 Wc4  = cmul(Wc2, Wc2);
            const float2 Wc8  = cmul(Wc4, Wc4);
            const float2 Wc16 = cmul(Wc8, Wc8);
            cst[n][7] = Wc;   cst[n][8] = Wc2;  cst[n][9] = Wc4;
            cst[n][10] = Wc8; cst[n][11] = Wc16;
        }
    }
    __syncthreads();

    const int n = lid;

    // ---- stage 2a: A rows i = 16*wid .. 16*wid+15 (2*Cd * E^i, fp16) ----
    {
        const float2 E   = cst[n][1];
        const float2 E2  = cst[n][2];
        const float2 E4  = cst[n][3];
        const float2 E8  = cst[n][4];
        float2 base = cst[n][0];                     // 2*Cd
        if (wid & 1) base = cmul(base, cst[n][5]);   // E^16
        if (wid & 2) base = cmul(base, cst[n][6]);   // E^32
        float2 z[16];
        z[0] = base;
        z[1] = cmul(base, E);
        z[2] = cmul(base, E2);
        z[4] = cmul(base, E4);
        z[3] = cmul(z[1], E2);
        z[5] = cmul(z[1], E4);
        z[6] = cmul(z[2], E4);
        z[7] = cmul(z[3], E4);
        #pragma unroll
        for (int s = 0; s < 8; s++) z[8 + s] = cmul(z[s], E8);
        #pragma unroll
        for (int s = 0; s < 16; s++) {
            const int i = wid * 16 + s;
            ((__half2*)(Am + i * LDA))[n] = __floats2half2_rn(z[s].x, z[s].y);
        }
    }

    // ---- stage 2b: B cols j = 8*wid .. 8*wid+7 (conj(W)^j, fp16) ----
    {
        const float2 W  = cst[n][7];
        const float2 W2 = cst[n][8];
        const float2 W4 = cst[n][9];
        float2 base = make_float2(1.0f, 0.0f);
        if (wid & 1) base = cst[n][10];              // Wc^8
        if (wid & 2) base = cmul(base, cst[n][11]);  // Wc^16
        float2 w[8];
        w[0] = base;
        w[1] = cmul(base, W);
        w[2] = cmul(base, W2);
        w[4] = cmul(base, W4);
        w[3] = cmul(w[1], W2);
        w[5] = cmul(w[1], W4);
        w[6] = cmul(w[2], W4);
        w[7] = cmul(w[3], W4);
        #pragma unroll
        for (int s = 0; s < 8; s++) {
            const int j = wid * 8 + s;
            ((__half2*)(Bm + j * LDA))[n] = __floats2half2_rn(w[s].x, w[s].y);
        }
    }
    __syncthreads();

    // ---- stage 3: WMMA, single pass. A fragments hoisted over jt ----
    {
        const int it = wid;
        wmma::fragment<wmma::matrix_a, 16, 16, 16, __half, wmma::row_major> af[4];
        #pragma unroll
        for (int kt = 0; kt < 4; kt++)
            wmma::load_matrix_sync(af[kt], Am + (it * 16) * LDA + kt * 16, LDA);

        #pragma unroll
        for (int jt = 0; jt < 2; jt++) {
            wmma::fragment<wmma::matrix_b, 16, 16, 16, __half, wmma::col_major> bf;
            wmma::fragment<wmma::accumulator, 16, 16, 16, float> acc;
            wmma::fill_fragment(acc, 0.0f);
            #pragma unroll
            for (int kt = 0; kt < 4; kt++) {
                wmma::load_matrix_sync(bf, Bm + (jt * 16) * LDA + kt * 16, LDA);
                wmma::mma_sync(acc, af[kt], bf, acc);
            }
            // out element (i, j) at out[h*2048 + j*64 + i] -> col-major, ld 64
            float* op = out + (size_t)h * 2048 + (size_t)(jt * 16) * 64 + it * 16;
            wmma::store_matrix_sync(op, acc, 64, wmma::mem_col_major);
        }
    }
}

// ---------------- generic fallback (any H, N2, L) ----------------
__global__ void s4d_fallback(
    const float* __restrict__ log_dt,
    const float* __restrict__ Cr,
    const float* __restrict__ logAre,
    const float* __restrict__ Aimag,
    float* __restrict__ out, int H, int N2, int L)
{
    const long long idx = (long long)blockIdx.x * blockDim.x + threadIdx.x;
    if (idx >= (long long)H * L) return;
    const int h = (int)(idx / L);
    const int l = (int)(idx % L);
    const float dt = __expf(log_dt[h]);
    const float lf = (float)l;
    float acc = 0.0f;
    for (int n = 0; n < N2; n++) {
        const float Are = -__expf(logAre[h * N2 + n]);
        const float Ai  = Aimag[h * N2 + n];
        const float dre = Are * dt;
        const float dim = Ai * dt;
        float s1, c1;
        __sincosf(dim, &s1, &c1);
        const float e1 = __expf(dre);
        const float numre = fmaf(e1, c1, -1.0f);
        const float numim = e1 * s1;
        const float inv  = __frcp_rn(fmaf(Are, Are, Ai * Ai));
        const float ccre = Cr[(h * N2 + n) * 2 + 0];
        const float ccim = Cr[(h * N2 + n) * 2 + 1];
        const float tre = ccre * numre - ccim * numim;
        const float tim = ccre * numim + ccim * numre;
        const float cdre = (tre * Are + tim * Ai) * inv;
        const float cdim = (tim * Are - tre * Ai) * inv;
        const float ph = red2pi(dim * lf);
        float s, c;
        __sincosf(ph, &s, &c);
        const float r = __expf(dre * lf);
        acc += r * (cdre * c - cdim * s);
    }
    out[idx] = 2.0f * acc;
}

extern "C" void kernel_launch(void* const* d_in, const int* in_sizes, int n_in,
                              void* d_out, int out_size)
{
    const float* log_dt = (const float*)d_in[0];
    const float* Cr     = (const float*)d_in[1];
    const float* lar    = (const float*)d_in[2];
    const float* aim    = (const float*)d_in[3];
    float* out = (float*)d_out;

    const int H  = in_sizes[0];
    const int N2 = (H > 0) ? in_sizes[2] / H : 0;
    const int L  = (H > 0) ? out_size / H : 0;

    if (N2 == 32 && L == 2048) {
        s4d_wmma<<<H, 128>>>(log_dt, Cr, lar, aim, out);
    } else {
        const long long total = (long long)H * L;
        const int blocks = (int)((total + 127) / 128);
        s4d_fallback<<<blocks, 128>>>(log_dt, Cr, lar, aim, out, H, N2, L);
    }
}